// round 12
// baseline (speedup 1.0000x reference)
#include <cuda_runtime.h>
#include <cuda_bf16.h>
#include <cstdint>
#include <cstddef>

// ============================================================================
// ConvLSTM encoder == 3-layer stacked LSTM (center tap only).
// Persistent kernel, GEMM on HMMA (mma.sync.m16n8k16 bf16, fp32 accum),
// bf16 hi/lo split x3 for fp32-grade accuracy. Target is plain sm_100
// (no tcgen05 -- confirmed by R11 ptxas errors).
//
// 144 CTAs = 3 layers x 3 batch-groups(88/88/80) x 16 hidden-chunks(8).
// Per CTA-step: D[96 batch(pad), 32 gates] = A[96,256] @ W[32,256]^T.
// Weights: B fragments PRE-PACKED IN REGISTERS (warp w = gate type w).
// A: staged from transposed bf16 hi/lo ring/x planes, ldmatrix.x4.trans.
// Cross-CTA sync: R9's proven flag protocol, watchdog-capped (no hangs).
// ============================================================================

#define LAYERS 3
#define JC_N   16
#define BG_N   3
#define CTA_PER_LAYER 48
#define GRID_MAIN 144
#define NTHR 256
#define RING 8
#define GSTR 100

// SMEM byte offsets
#define AROWB   208                       // 104 ushorts per k-row
#define SM_AHI  0
#define SM_ALO  (256*AROWB)               // 53248
#define SM_GSH  (2*256*AROWB)             // 106496 (32*GSTR floats)
#define SM_CSH  (SM_GSH + 32*GSTR*4)      // 119296 (88*8 floats)
#define SM_BIAS (SM_CSH + 88*8*4)         // 122112 (32 floats)
#define SMEM_BYTES (SM_BIAS + 128)        // 122240

__device__ unsigned short g_xhi[512][64][256];
__device__ unsigned short g_xlo[512][64][256];
__device__ unsigned short g_hhi[3][RING][128][256];
__device__ unsigned short g_hlo[3][RING][128][256];
__device__ __align__(64) int g_flags[3][3][16];
__device__ volatile int g_abort;

// ---------------------------------------------------------------------------
__device__ __forceinline__ uint32_t smem_u32(const void* p) {
    uint32_t a;
    asm("{ .reg .u64 t; cvta.to.shared.u64 t, %1; cvt.u32.u64 %0, t; }"
        : "=r"(a) : "l"(p));
    return a;
}

__device__ __forceinline__ void bsplit(float x, unsigned short& hi,
                                       unsigned short& lo) {
    __nv_bfloat16 h = __float2bfloat16(x);
    float r = x - __bfloat162float(h);
    __nv_bfloat16 l2 = __float2bfloat16(r);
    hi = __bfloat16_as_ushort(h);
    lo = __bfloat16_as_ushort(l2);
}

__device__ __forceinline__ void ld_rel4(uint4& v, const void* p) {
    asm volatile("ld.relaxed.gpu.global.v4.b32 {%0,%1,%2,%3}, [%4];"
                 : "=r"(v.x), "=r"(v.y), "=r"(v.z), "=r"(v.w) : "l"(p));
}

__device__ __forceinline__ void mma_bf16(float* c, const uint32_t* a,
                                         uint32_t b0, uint32_t b1) {
    asm volatile(
        "mma.sync.aligned.m16n8k16.row.col.f32.bf16.bf16.f32 "
        "{%0,%1,%2,%3}, {%4,%5,%6,%7}, {%8,%9}, {%0,%1,%2,%3};"
        : "+f"(c[0]), "+f"(c[1]), "+f"(c[2]), "+f"(c[3])
        : "r"(a[0]), "r"(a[1]), "r"(a[2]), "r"(a[3]), "r"(b0), "r"(b1));
}

__device__ __forceinline__ void ldm4t(uint32_t* a, uint32_t addr) {
    asm volatile(
        "ldmatrix.sync.aligned.m8n8.x4.trans.shared.b16 {%0,%1,%2,%3}, [%4];"
        : "=r"(a[0]), "=r"(a[1]), "=r"(a[2]), "=r"(a[3]) : "r"(addr));
}

// Poll 16 flags until all >= val. Cap 2^20 spins; abort-latch fast-path.
__device__ __forceinline__ void wait16(const int* p, int val) {
    if (g_abort) return;
    int spins = 0;
    while (true) {
        bool ok = true;
        #pragma unroll
        for (int i = 0; i < 4; ++i) {
            int4 v;
            asm volatile("ld.relaxed.gpu.global.v4.b32 {%0,%1,%2,%3}, [%4];"
                         : "=r"(v.x), "=r"(v.y), "=r"(v.z), "=r"(v.w)
                         : "l"(p + 4 * i));
            ok &= (v.x >= val) & (v.y >= val) & (v.z >= val) & (v.w >= val);
        }
        if (ok) return;
        if (((++spins) & 63) == 0) {
            if (g_abort) return;
            if (spins > (1 << 20)) { g_abort = 1; return; }
        }
        __nanosleep(32);
    }
}

// ---------------------------------------------------------------------------
__global__ void reset_kernel() {
    int i = threadIdx.x;
    if (i < 3 * 3 * 16) ((int*)g_flags)[i] = 0;
    if (i == 0) g_abort = 0;
}

// x[b][t][k] -> transposed bf16 hi/lo planes [t][k][b]
__global__ void ximg_kernel(const float* __restrict__ x, int T) {
    const int t = blockIdx.x;
    const int b = threadIdx.x;
    if (t >= 512) return;
    const float* src = x + ((size_t)b * T + t) * 64;
    #pragma unroll 4
    for (int k = 0; k < 64; ++k) {
        unsigned short hi, lo;
        bsplit(src[k], hi, lo);
        g_xhi[t][k][b] = hi;
        g_xlo[t][k][b] = lo;
    }
}

// h0 -> ring slot RING-1, transposed hi/lo planes
__global__ void ringinit_kernel(const float* __restrict__ h01,
                                const float* __restrict__ h02,
                                const float* __restrict__ h03) {
    const int l = blockIdx.x, j0 = blockIdx.y * 16;
    const float* h0 = (l == 0) ? h01 : ((l == 1) ? h02 : h03);
    for (int u = threadIdx.x; u < 16 * 256; u += 256) {
        const int jj = u >> 8, b = u & 255;
        unsigned short hi, lo;
        bsplit(h0[(size_t)b * 128 + j0 + jj], hi, lo);
        g_hhi[l][RING - 1][j0 + jj][b] = hi;
        g_hlo[l][RING - 1][j0 + jj][b] = lo;
    }
}

// ---------------------------------------------------------------------------
__global__ void __launch_bounds__(NTHR, 1)
lstm_hmma(const float* __restrict__ W1, const float* __restrict__ b1,
          const float* __restrict__ W2, const float* __restrict__ b2,
          const float* __restrict__ W3, const float* __restrict__ b3,
          const float* __restrict__ c01, const float* __restrict__ c02,
          const float* __restrict__ c03,
          float* __restrict__ out, int T)
{
    extern __shared__ __align__(16) unsigned char sm[];
    const int tid  = threadIdx.x;
    const int wid  = tid >> 5;
    const int lane = tid & 31;
    const int l    = blockIdx.x / CTA_PER_LAYER;
    const int rr   = blockIdx.x % CTA_PER_LAYER;
    const int jc   = rr & 15;
    const int bg   = rr >> 4;
    const int b0   = bg * 88;
    const int bcnt = (bg == 2) ? 80 : 88;
    const int Kin  = (l == 0) ? 64 : 128;
    const int K    = Kin + 128;
    const int nkt  = K >> 4;                      // 12 or 16

    const float* Wl  = (l == 0) ? W1 : ((l == 1) ? W2 : W3);
    const float* bl  = (l == 0) ? b1 : ((l == 1) ? b2 : b3);
    const float* c0l = (l == 0) ? c01 : ((l == 1) ? c02 : c03);

    float* Gsh  = reinterpret_cast<float*>(sm + SM_GSH);
    float* Csh  = reinterpret_cast<float*>(sm + SM_CSH);
    float* Bsh  = reinterpret_cast<float*>(sm + SM_BIAS);
    const uint32_t aHI = smem_u32(sm + SM_AHI);
    const uint32_t aLO = smem_u32(sm + SM_ALO);

    // ---- one-time init ----------------------------------------------------
    // B fragments in registers: warp w = gate type w, lane: grp=lane>>2 (=j),
    // tig=lane&3. b0 packs k = kt*16+2tig, +1; b1 packs k+8, +9.
    uint32_t bH0[16], bH1[16], bL0[16], bL1[16];
    if (wid < 4) {
        const int grp = lane >> 2, tig = lane & 3;
        const int o = wid * 128 + jc * 8 + grp;
        const float* Wr = Wl + (size_t)o * K * 3 + 1;   // center tap, stride 3
        #pragma unroll
        for (int kt = 0; kt < 16; ++kt) {
            if (kt < nkt) {
                const int k0 = kt * 16 + 2 * tig;
                unsigned short h0, l0, h1, l1;
                bsplit(Wr[(k0    ) * 3], h0, l0);
                bsplit(Wr[(k0 + 1) * 3], h1, l1);
                bH0[kt] = (uint32_t)h0 | ((uint32_t)h1 << 16);
                bL0[kt] = (uint32_t)l0 | ((uint32_t)l1 << 16);
                bsplit(Wr[(k0 + 8) * 3], h0, l0);
                bsplit(Wr[(k0 + 9) * 3], h1, l1);
                bH1[kt] = (uint32_t)h0 | ((uint32_t)h1 << 16);
                bL1[kt] = (uint32_t)l0 | ((uint32_t)l1 << 16);
            } else {
                bH0[kt] = bH1[kt] = bL0[kt] = bL1[kt] = 0u;
            }
        }
    }
    if (tid < 32)
        Bsh[tid] = bl[(tid >> 3) * 128 + jc * 8 + (tid & 7)];
    for (int i = tid; i < 8 * bcnt; i += NTHR) {
        const int jj = i & 7, m = i >> 3;
        Csh[i] = c0l[(size_t)(b0 + m) * 128 + jc * 8 + jj];
    }
    // layer0: zero A rows 192..255 (both planes) once -- K-pad reads as 0
    if (l == 0) {
        for (int u = tid; u < 64 * 13; u += NTHR) {
            const int k = 192 + u / 13, c = u % 13;
            *reinterpret_cast<uint4*>(sm + SM_AHI + k * AROWB + c * 16) =
                make_uint4(0, 0, 0, 0);
            *reinterpret_cast<uint4*>(sm + SM_ALO + k * AROWB + c * 16) =
                make_uint4(0, 0, 0, 0);
        }
    }
    __syncthreads();

    int* myflag = &g_flags[l][bg][jc];
    const int* flag_own  = &g_flags[l][bg][0];
    const int* flag_low  = (l > 0) ? &g_flags[l - 1][bg][0] : nullptr;
    const int* flag_down = (l < 2) ? &g_flags[l + 1][bg][0] : nullptr;

    // ldmatrix lane address components (trans: SMEM is [k][m])
    const int lrow  = lane & 7;
    const int lkoff = ((lane >> 4) & 1) * 8;
    const int lmoff = ((lane >> 3) & 1) * 8;

    for (int t = 0; t < T; ++t) {
        // ---- dependency waits --------------------------------------------
        if (tid == 0) {
            if (t > 0)              wait16(flag_own, t);
            if (l > 0)              wait16(flag_low, t + 1);
            if (l < 2 && t >= RING) wait16(flag_down, t - RING + 1);
            asm volatile("fence.acq_rel.gpu;" ::: "memory");
        }
        __syncthreads();
        const int slot  = t & (RING - 1);
        const int pslot = (t - 1) & (RING - 1);

        // ---- stage A planes [k][m] (bf16), 16B chunks, zero m-pad --------
        {
            const int nch = K * 12;          // 12 chunks of 8 cols per k-row
            for (int u = tid; u < 2 * nch; u += NTHR) {
                const int p = (u >= nch);
                const int v = p ? u - nch : u;
                const int k = v / 12, c = v % 12;
                uint4 val;
                if (c * 8 >= bcnt) {
                    val = make_uint4(0, 0, 0, 0);
                } else {
                    const unsigned short* src;
                    if (k < Kin) {
                        if (l == 0)
                            src = p ? &g_xlo[t][k][b0] : &g_xhi[t][k][b0];
                        else
                            src = p ? &g_hlo[l - 1][slot][k][b0]
                                    : &g_hhi[l - 1][slot][k][b0];
                    } else {
                        src = p ? &g_hlo[l][pslot][k - Kin][b0]
                                : &g_hhi[l][pslot][k - Kin][b0];
                    }
                    ld_rel4(val, src + c * 8);
                }
                *reinterpret_cast<uint4*>(
                    sm + (p ? SM_ALO : SM_AHI) + k * AROWB + c * 16) = val;
            }
        }
        __syncthreads();

        // ---- GEMM: warps 0-3, 6 m-tiles x 16 k-tiles x 3 passes ----------
        if (wid < 4) {
            const int grp = lane >> 2, tig = lane & 3;
            float c[6][4];
            #pragma unroll
            for (int mt = 0; mt < 6; ++mt) {
                c[mt][0] = c[mt][1] = c[mt][2] = c[mt][3] = 0.f;
                const uint32_t mo = (mt * 16 + lmoff) * 2;
                uint32_t a[4];
                #pragma unroll
                for (int kt = 0; kt < 16; ++kt) {
                    ldm4t(a, aHI + (kt * 16 + lkoff + lrow) * AROWB + mo);
                    mma_bf16(c[mt], a, bH0[kt], bH1[kt]);
                    mma_bf16(c[mt], a, bL0[kt], bL1[kt]);
                }
                #pragma unroll
                for (int kt = 0; kt < 16; ++kt) {
                    ldm4t(a, aLO + (kt * 16 + lkoff + lrow) * AROWB + mo);
                    mma_bf16(c[mt], a, bH0[kt], bH1[kt]);
                }
                // store: rows n = wid*8 + 2tig(+1); cols m = mt*16+grp(+8)
                const int rn = wid * 8 + 2 * tig;
                const int m0 = mt * 16 + grp;
                Gsh[(rn    ) * GSTR + m0    ] = c[mt][0];
                Gsh[(rn + 1) * GSTR + m0    ] = c[mt][1];
                Gsh[(rn    ) * GSTR + m0 + 8] = c[mt][2];
                Gsh[(rn + 1) * GSTR + m0 + 8] = c[mt][3];
            }
        }
        __syncthreads();

        // ---- pointwise LSTM; publish h (bf16 hi/lo, transposed ring) -----
        for (int i = tid; i < 8 * bcnt; i += NTHR) {
            const int jj = i & 7, m = i >> 3;
            const float gi = Gsh[(     jj) * GSTR + m] + Bsh[     jj];
            const float gf = Gsh[( 8 + jj) * GSTR + m] + Bsh[ 8 + jj];
            const float go = Gsh[(16 + jj) * GSTR + m] + Bsh[16 + jj];
            const float gg = Gsh[(24 + jj) * GSTR + m] + Bsh[24 + jj];
            float c = Csh[i];
            const float si = __fdividef(1.f, 1.f + __expf(-gi));
            const float sf = __fdividef(1.f, 1.f + __expf(-gf));
            const float so = __fdividef(1.f, 1.f + __expf(-go));
            c = sf * c + si * tanhf(gg);
            const float h = so * tanhf(c);
            Csh[i] = c;
            unsigned short hh, hl;
            bsplit(h, hh, hl);
            g_hhi[l][slot][jc * 8 + jj][b0 + m] = hh;
            g_hlo[l][slot][jc * 8 + jj][b0 + m] = hl;
            if (l == 2 && t == T - 1)
                out[(size_t)(b0 + m) * 128 + jc * 8 + jj] = h;
        }

        asm volatile("fence.acq_rel.gpu;" ::: "memory");
        __syncthreads();
        if (tid == 0)
            asm volatile("st.relaxed.gpu.global.s32 [%0], %1;"
                         :: "l"(myflag), "r"(t + 1) : "memory");
    }
}

// ---------------------------------------------------------------------------
extern "C" void kernel_launch(void* const* d_in, const int* in_sizes, int n_in,
                              void* d_out, int out_size)
{
    const float* x   = (const float*)d_in[0];
    const float* W1  = (const float*)d_in[1];
    const float* b1  = (const float*)d_in[2];
    const float* W2  = (const float*)d_in[3];
    const float* b2  = (const float*)d_in[4];
    const float* W3  = (const float*)d_in[5];
    const float* b3  = (const float*)d_in[6];
    const float* h01 = (const float*)d_in[7];
    const float* c01 = (const float*)d_in[8];
    const float* h02 = (const float*)d_in[9];
    const float* c02 = (const float*)d_in[10];
    const float* h03 = (const float*)d_in[11];
    const float* c03 = (const float*)d_in[12];
    float* out = (float*)d_out;
    (void)n_in; (void)out_size;

    const int T = in_sizes[0] / (256 * 64);   // = 512

    cudaFuncSetAttribute(lstm_hmma,
                         cudaFuncAttributeMaxDynamicSharedMemorySize,
                         SMEM_BYTES);

    reset_kernel<<<1, 256>>>();
    ximg_kernel<<<T, 256>>>(x, T);
    ringinit_kernel<<<dim3(3, 8), 256>>>(h01, h02, h03);
    lstm_hmma<<<GRID_MAIN, NTHR, SMEM_BYTES>>>(
        W1, b1, W2, b2, W3, b3, c01, c02, c03, out, T);
}